// round 2
// baseline (speedup 1.0000x reference)
#include <cuda_runtime.h>
#include <math.h>

// Problem constants
#define B_    4096
#define T_    50
#define I_    17
#define H_    256
#define P_    20
#define M_    32            // batch rows per CTA
#define MT_   8             // row tile per accumulator group
#define NG_   (M_ / MT_)    // 4 groups
#define NCTA_ (B_ / M_)     // 128 CTAs
#define NTHR_ 256           // one thread per hidden column j

#define DT_   0.1f
#define IMGW_ 1920.0f
#define IMGH_ 1080.0f
// sqrt(1920^2 + 1080^2)
#define DIAG_ 2202.9071700822507f

struct Smem {
    float h0[2][M_][H_];   // layer-0 hidden, double buffered
    float h1[2][M_][H_];   // layer-1 hidden, double buffered
    float c0[M_][H_];      // layer-0 cell (thread-private cells)
    float c1[M_][H_];      // layer-1 cell
    float xs[M_][I_];      // current timestep input slice
    float raw[M_][2 * P_]; // FC outputs
};
// floats: 16384+16384+8192+8192+544+1280 = 50976 -> 203904 bytes
#define SMEM_BYTES (sizeof(Smem))

__device__ __forceinline__ float sigf(float x) {
    // 1/(1+e^-x); __expf(-x)->inf for very negative x gives 0, ->0 gives 1. Safe.
    return __fdividef(1.f, 1.f + __expf(-x));
}
__device__ __forceinline__ float tanhf_(float x) {
    // 2*sigmoid(2x)-1; saturates cleanly at +-1, abs err ~1e-7 near 0.
    return __fdividef(2.f, 1.f + __expf(-2.f * x)) - 1.f;
}

__global__ void __launch_bounds__(NTHR_, 1)
lstm_kin_kernel(const float* __restrict__ x,
                const float* __restrict__ wih0, const float* __restrict__ whh0,
                const float* __restrict__ bih0, const float* __restrict__ bhh0,
                const float* __restrict__ wih1, const float* __restrict__ whh1,
                const float* __restrict__ bih1, const float* __restrict__ bhh1,
                const float* __restrict__ fcw,  const float* __restrict__ fcb,
                float* __restrict__ out)
{
    extern __shared__ float smem_raw[];
    Smem* S = reinterpret_cast<Smem*>(smem_raw);

    const int tid  = threadIdx.x;
    const int j    = tid;                 // hidden column owned by this thread
    const int row0 = blockIdx.x * M_;

    // Combined biases for this thread's 4 gate rows (gate g -> row g*H + j)
    float bias0[4], bias1[4];
#pragma unroll
    for (int g = 0; g < 4; ++g) {
        bias0[g] = bih0[g * H_ + j] + bhh0[g * H_ + j];
        bias1[g] = bih1[g * H_ + j] + bhh1[g * H_ + j];
    }

    // Zero initial state
#pragma unroll 4
    for (int m = 0; m < M_; ++m) {
        S->h0[0][m][j] = 0.f;
        S->h1[0][m][j] = 0.f;
        S->c0[m][j]    = 0.f;
        S->c1[m][j]    = 0.f;
    }
    // Load x slice for t = 0
    for (int idx = tid; idx < M_ * I_; idx += NTHR_) {
        int m = idx / I_, k = idx % I_;
        S->xs[m][k] = x[((size_t)(row0 + m) * T_ + 0) * I_ + k];
    }
    __syncthreads();

    // Per-gate weight row base pointers (rows g*H + j)
    const float* wi0r[4];
    const float* w0r[4];
    const float* wi1r[4];
    const float* w1r[4];
#pragma unroll
    for (int g = 0; g < 4; ++g) {
        wi0r[g] = wih0 + (size_t)(g * H_ + j) * I_;
        w0r[g]  = whh0 + (size_t)(g * H_ + j) * H_;
        wi1r[g] = wih1 + (size_t)(g * H_ + j) * H_;
        w1r[g]  = whh1 + (size_t)(g * H_ + j) * H_;
    }

    int cur = 0;
    for (int t = 0; t < T_; ++t) {
        const int nxt = cur ^ 1;

        // ================= layer 0 =================
#pragma unroll 1
        for (int gb = 0; gb < NG_; ++gb) {
            float acc[MT_][4];
#pragma unroll
            for (int mt = 0; mt < MT_; ++mt)
#pragma unroll
                for (int g = 0; g < 4; ++g) acc[mt][g] = bias0[g];

            // input contribution (K = 17)
#pragma unroll
            for (int k = 0; k < I_; ++k) {
                float wv0 = wi0r[0][k], wv1 = wi0r[1][k];
                float wv2 = wi0r[2][k], wv3 = wi0r[3][k];
#pragma unroll
                for (int mt = 0; mt < MT_; ++mt) {
                    float xv = S->xs[gb * MT_ + mt][k];  // broadcast
                    acc[mt][0] += wv0 * xv;
                    acc[mt][1] += wv1 * xv;
                    acc[mt][2] += wv2 * xv;
                    acc[mt][3] += wv3 * xv;
                }
            }
            // recurrent contribution (K = 256)
#pragma unroll 2
            for (int kc = 0; kc < H_; kc += 8) {
                float4 wA[4], wB[4];
#pragma unroll
                for (int g = 0; g < 4; ++g) {
                    wA[g] = *reinterpret_cast<const float4*>(w0r[g] + kc);
                    wB[g] = *reinterpret_cast<const float4*>(w0r[g] + kc + 4);
                }
#pragma unroll
                for (int mt = 0; mt < MT_; ++mt) {
                    const float* hp = &S->h0[cur][gb * MT_ + mt][kc];
                    float4 hA = *reinterpret_cast<const float4*>(hp);
                    float4 hB = *reinterpret_cast<const float4*>(hp + 4);
#pragma unroll
                    for (int g = 0; g < 4; ++g) {
                        acc[mt][g] += wA[g].x * hA.x + wA[g].y * hA.y +
                                      wA[g].z * hA.z + wA[g].w * hA.w;
                        acc[mt][g] += wB[g].x * hB.x + wB[g].y * hB.y +
                                      wB[g].z * hB.z + wB[g].w * hB.w;
                    }
                }
            }
            // activations + state update
#pragma unroll
            for (int mt = 0; mt < MT_; ++mt) {
                int m = gb * MT_ + mt;
                float ig = sigf(acc[mt][0]);
                float fg = sigf(acc[mt][1]);
                float gv = tanhf_(acc[mt][2]);
                float og = sigf(acc[mt][3]);
                float c  = fg * S->c0[m][j] + ig * gv;
                S->c0[m][j]       = c;
                S->h0[nxt][m][j]  = og * tanhf_(c);
            }
        }
        __syncthreads();   // h0[nxt] complete; all reads of h0[cur]/xs done

        // ================= layer 1 =================
#pragma unroll 1
        for (int gb = 0; gb < NG_; ++gb) {
            float acc[MT_][4];
#pragma unroll
            for (int mt = 0; mt < MT_; ++mt)
#pragma unroll
                for (int g = 0; g < 4; ++g) acc[mt][g] = bias1[g];

            // input contribution: w_ih1 x h0[nxt]  (K = 256)
#pragma unroll 2
            for (int kc = 0; kc < H_; kc += 8) {
                float4 wA[4], wB[4];
#pragma unroll
                for (int g = 0; g < 4; ++g) {
                    wA[g] = *reinterpret_cast<const float4*>(wi1r[g] + kc);
                    wB[g] = *reinterpret_cast<const float4*>(wi1r[g] + kc + 4);
                }
#pragma unroll
                for (int mt = 0; mt < MT_; ++mt) {
                    const float* hp = &S->h0[nxt][gb * MT_ + mt][kc];
                    float4 hA = *reinterpret_cast<const float4*>(hp);
                    float4 hB = *reinterpret_cast<const float4*>(hp + 4);
#pragma unroll
                    for (int g = 0; g < 4; ++g) {
                        acc[mt][g] += wA[g].x * hA.x + wA[g].y * hA.y +
                                      wA[g].z * hA.z + wA[g].w * hA.w;
                        acc[mt][g] += wB[g].x * hB.x + wB[g].y * hB.y +
                                      wB[g].z * hB.z + wB[g].w * hB.w;
                    }
                }
            }
            // recurrent contribution: w_hh1 x h1[cur]  (K = 256)
#pragma unroll 2
            for (int kc = 0; kc < H_; kc += 8) {
                float4 wA[4], wB[4];
#pragma unroll
                for (int g = 0; g < 4; ++g) {
                    wA[g] = *reinterpret_cast<const float4*>(w1r[g] + kc);
                    wB[g] = *reinterpret_cast<const float4*>(w1r[g] + kc + 4);
                }
#pragma unroll
                for (int mt = 0; mt < MT_; ++mt) {
                    const float* hp = &S->h1[cur][gb * MT_ + mt][kc];
                    float4 hA = *reinterpret_cast<const float4*>(hp);
                    float4 hB = *reinterpret_cast<const float4*>(hp + 4);
#pragma unroll
                    for (int g = 0; g < 4; ++g) {
                        acc[mt][g] += wA[g].x * hA.x + wA[g].y * hA.y +
                                      wA[g].z * hA.z + wA[g].w * hA.w;
                        acc[mt][g] += wB[g].x * hB.x + wB[g].y * hB.y +
                                      wB[g].z * hB.z + wB[g].w * hB.w;
                    }
                }
            }
#pragma unroll
            for (int mt = 0; mt < MT_; ++mt) {
                int m = gb * MT_ + mt;
                float ig = sigf(acc[mt][0]);
                float fg = sigf(acc[mt][1]);
                float gv = tanhf_(acc[mt][2]);
                float og = sigf(acc[mt][3]);
                float c  = fg * S->c1[m][j] + ig * gv;
                S->c1[m][j]       = c;
                S->h1[nxt][m][j]  = og * tanhf_(c);
            }
        }

        // prefetch next timestep's x slice (xs readers finished before sync above)
        if (t + 1 < T_) {
            for (int idx = tid; idx < M_ * I_; idx += NTHR_) {
                int m = idx / I_, k = idx % I_;
                S->xs[m][k] = x[((size_t)(row0 + m) * T_ + (t + 1)) * I_ + k];
            }
        }
        __syncthreads();   // h1[nxt] + xs ready
        cur = nxt;
    }

    // ================= FC head: raw[m][q] = h1 . fcw[q] + fcb[q] =================
    for (int idx = tid; idx < M_ * 2 * P_; idx += NTHR_) {
        int m = idx / (2 * P_), q = idx % (2 * P_);
        const float* wq = fcw + (size_t)q * H_;
        const float* hq = &S->h1[cur][m][0];
        float s = fcb[q];
#pragma unroll 4
        for (int k = 0; k < H_; k += 4) {
            float4 w4 = *reinterpret_cast<const float4*>(wq + k);
            float4 h4 = *reinterpret_cast<const float4*>(hq + k);
            s += w4.x * h4.x + w4.y * h4.y + w4.z * h4.z + w4.w * h4.w;
        }
        S->raw[m][q] = s;
    }
    __syncthreads();

    // ================= kinematic rollout (1 thread per row) =================
    if (tid < M_) {
        const int m   = tid;
        const int row = row0 + m;
        const float* xl = x + ((size_t)row * T_ + (T_ - 1)) * I_;
        float psi = atan2f(xl[7], xl[8]);
        float X   = xl[0] * IMGW_;
        float Y   = xl[1] * IMGH_;
        float decay = 1.f;
        float* o = out + (size_t)row * P_ * 2;
#pragma unroll 1
        for (int p = 0; p < P_; ++p) {
            float sraw = S->raw[m][2 * p];
            float yaw  = S->raw[m][2 * p + 1];
            // softplus = max(x,0) + log1p(exp(-|x|))
            float speed = fmaxf(sraw, 0.f) + log1pf(expf(-fabsf(sraw)));
            float w = yaw * decay;
            decay *= 0.97f;
            float v = speed * DIAG_;
            float psi_prev  = psi;
            float psi_after = psi + w * DT_;
            psi = psi_after;
            float is_s  = (fabsf(w) < 0.01f) ? 1.f : 0.f;
            float wsafe = w + is_s * 0.0001f;
            float radius = v / wsafe;
            float sp = sinf(psi_prev),  cp = cosf(psi_prev);
            float sa = sinf(psi_after), ca = cosf(psi_after);
            float dxs = v * cp * DT_;
            float dys = v * sp * DT_;
            float dxt = radius * (sa - sp);
            float dyt = -radius * (ca - cp);
            float dx = is_s * dxs + (1.f - is_s) * dxt;
            float dy = is_s * dys + (1.f - is_s) * dyt;
            X += dx;
            Y += dy;
            o[2 * p]     = X / IMGW_;
            o[2 * p + 1] = Y / IMGH_;
        }
    }
}

extern "C" void kernel_launch(void* const* d_in, const int* in_sizes, int n_in,
                              void* d_out, int out_size)
{
    (void)in_sizes; (void)n_in; (void)out_size;
    const float* x    = (const float*)d_in[0];
    const float* wih0 = (const float*)d_in[1];
    const float* whh0 = (const float*)d_in[2];
    const float* bih0 = (const float*)d_in[3];
    const float* bhh0 = (const float*)d_in[4];
    const float* wih1 = (const float*)d_in[5];
    const float* whh1 = (const float*)d_in[6];
    const float* bih1 = (const float*)d_in[7];
    const float* bhh1 = (const float*)d_in[8];
    const float* fcw  = (const float*)d_in[9];
    const float* fcb  = (const float*)d_in[10];
    float* out = (float*)d_out;

    cudaFuncSetAttribute(lstm_kin_kernel,
                         cudaFuncAttributeMaxDynamicSharedMemorySize,
                         (int)SMEM_BYTES);

    lstm_kin_kernel<<<NCTA_, NTHR_, SMEM_BYTES>>>(
        x, wih0, whh0, bih0, bhh0, wih1, whh1, bih1, bhh1, fcw, fcb, out);
}

// round 3
// speedup vs baseline: 2.8499x; 2.8499x over previous
#include <cuda_runtime.h>
#include <math.h>

// Problem constants
#define B_    4096
#define T_    50
#define I_    17
#define H_    256
#define P_    20
#define M_    32            // batch rows per CTA
#define MT_   8             // row tile per accumulator group
#define NG_   (M_ / MT_)    // 4 groups
#define NCTA_ (B_ / M_)     // 128 CTAs
#define NTHR_ 256           // one thread per hidden column j
#define G4_   (4 * H_)      // 1024 gate rows

#define DT_   0.1f
#define IMGW_ 1920.0f
#define IMGH_ 1080.0f
#define DIAG_ 2202.9071700822507f

// ---------------- transposed-weight scratch (K-major, float4-packed) ----------
// wT[k4][r] = float4( w[r][4*k4 + 0..3] ),  r = g*H + j  (r in [0,1024))
// Lane-consecutive j -> 16B-strided addresses -> fully coalesced LDG.128.
__device__ float4 g_w0h[64 * G4_];   // whh0 transposed   (1 MB)
__device__ float4 g_w1i[64 * G4_];   // wih1 transposed   (1 MB)
__device__ float4 g_w1h[64 * G4_];   // whh1 transposed   (1 MB)
__device__ float  g_w0i[I_ * G4_];   // wih0 transposed: g_w0i[k*1024 + r] (68 KB)

__global__ void prep_kernel(const float* __restrict__ whh0,
                            const float* __restrict__ wih1,
                            const float* __restrict__ whh1,
                            const float* __restrict__ wih0)
{
    int idx = blockIdx.x * blockDim.x + threadIdx.x;   // 0 .. 65535
    if (idx < 64 * G4_) {
        int k4 = idx >> 10;            // 0..63
        int r  = idx & (G4_ - 1);      // 0..1023
        const float4* s0 = reinterpret_cast<const float4*>(whh0);
        const float4* s1 = reinterpret_cast<const float4*>(wih1);
        const float4* s2 = reinterpret_cast<const float4*>(whh1);
        g_w0h[idx] = s0[r * 64 + k4];  // contiguous 16B read from row r
        g_w1i[idx] = s1[r * 64 + k4];
        g_w1h[idx] = s2[r * 64 + k4];
    }
    if (idx < I_ * G4_) {
        int k = idx >> 10;
        int r = idx & (G4_ - 1);
        g_w0i[idx] = wih0[r * I_ + k];
    }
}

// ------------------------------ main kernel ----------------------------------
struct Smem {
    float h0[2][M_][H_];   // layer-0 hidden, double buffered
    float h1[2][M_][H_];   // layer-1 hidden, double buffered
    float c0[M_][H_];      // layer-0 cell
    float c1[M_][H_];      // layer-1 cell
    float xs[M_][I_];      // current timestep input slice
    float raw[M_][2 * P_]; // FC outputs
};
#define SMEM_BYTES (sizeof(Smem))

__device__ __forceinline__ float sigf(float x) {
    return __fdividef(1.f, 1.f + __expf(-x));
}
__device__ __forceinline__ float tanhf_(float x) {
    return __fdividef(2.f, 1.f + __expf(-2.f * x)) - 1.f;
}

__global__ void __launch_bounds__(NTHR_, 1)
lstm_kin_kernel(const float* __restrict__ x,
                const float* __restrict__ bih0, const float* __restrict__ bhh0,
                const float* __restrict__ bih1, const float* __restrict__ bhh1,
                const float* __restrict__ fcw,  const float* __restrict__ fcb,
                float* __restrict__ out)
{
    extern __shared__ float smem_raw[];
    Smem* S = reinterpret_cast<Smem*>(smem_raw);

    const int tid  = threadIdx.x;
    const int j    = tid;                 // hidden column owned by this thread
    const int row0 = blockIdx.x * M_;

    float bias0[4], bias1[4];
#pragma unroll
    for (int g = 0; g < 4; ++g) {
        bias0[g] = bih0[g * H_ + j] + bhh0[g * H_ + j];
        bias1[g] = bih1[g * H_ + j] + bhh1[g * H_ + j];
    }

#pragma unroll 4
    for (int m = 0; m < M_; ++m) {
        S->h0[0][m][j] = 0.f;
        S->h1[0][m][j] = 0.f;
        S->c0[m][j]    = 0.f;
        S->c1[m][j]    = 0.f;
    }
    for (int idx = tid; idx < M_ * I_; idx += NTHR_) {
        int m = idx / I_, k = idx % I_;
        S->xs[m][k] = x[((size_t)(row0 + m) * T_ + 0) * I_ + k];
    }
    __syncthreads();

    int cur = 0;
    for (int t = 0; t < T_; ++t) {
        const int nxt = cur ^ 1;

        // ================= layer 0 =================
#pragma unroll 1
        for (int gb = 0; gb < NG_; ++gb) {
            float acc[MT_][4];
#pragma unroll
            for (int mt = 0; mt < MT_; ++mt)
#pragma unroll
                for (int g = 0; g < 4; ++g) acc[mt][g] = bias0[g];

            // input contribution (K = 17), coalesced scalar loads
#pragma unroll
            for (int k = 0; k < I_; ++k) {
                float wv0 = g_w0i[k * G4_ + 0 * H_ + j];
                float wv1 = g_w0i[k * G4_ + 1 * H_ + j];
                float wv2 = g_w0i[k * G4_ + 2 * H_ + j];
                float wv3 = g_w0i[k * G4_ + 3 * H_ + j];
#pragma unroll
                for (int mt = 0; mt < MT_; ++mt) {
                    float xv = S->xs[gb * MT_ + mt][k];
                    acc[mt][0] += wv0 * xv;
                    acc[mt][1] += wv1 * xv;
                    acc[mt][2] += wv2 * xv;
                    acc[mt][3] += wv3 * xv;
                }
            }
            // recurrent contribution (K = 256), transposed coalesced weights
#pragma unroll 2
            for (int kc4 = 0; kc4 < 64; ++kc4) {
                float4 w[4];
#pragma unroll
                for (int g = 0; g < 4; ++g)
                    w[g] = g_w0h[kc4 * G4_ + g * H_ + j];
#pragma unroll
                for (int mt = 0; mt < MT_; ++mt) {
                    float4 h = *reinterpret_cast<const float4*>(
                        &S->h0[cur][gb * MT_ + mt][kc4 * 4]);
#pragma unroll
                    for (int g = 0; g < 4; ++g)
                        acc[mt][g] += w[g].x * h.x + w[g].y * h.y +
                                      w[g].z * h.z + w[g].w * h.w;
                }
            }
#pragma unroll
            for (int mt = 0; mt < MT_; ++mt) {
                int m = gb * MT_ + mt;
                float ig = sigf(acc[mt][0]);
                float fg = sigf(acc[mt][1]);
                float gv = tanhf_(acc[mt][2]);
                float og = sigf(acc[mt][3]);
                float c  = fg * S->c0[m][j] + ig * gv;
                S->c0[m][j]       = c;
                S->h0[nxt][m][j]  = og * tanhf_(c);
            }
        }
        __syncthreads();

        // ================= layer 1 =================
#pragma unroll 1
        for (int gb = 0; gb < NG_; ++gb) {
            float acc[MT_][4];
#pragma unroll
            for (int mt = 0; mt < MT_; ++mt)
#pragma unroll
                for (int g = 0; g < 4; ++g) acc[mt][g] = bias1[g];

            // input contribution: wih1 x h0[nxt]
#pragma unroll 2
            for (int kc4 = 0; kc4 < 64; ++kc4) {
                float4 w[4];
#pragma unroll
                for (int g = 0; g < 4; ++g)
                    w[g] = g_w1i[kc4 * G4_ + g * H_ + j];
#pragma unroll
                for (int mt = 0; mt < MT_; ++mt) {
                    float4 h = *reinterpret_cast<const float4*>(
                        &S->h0[nxt][gb * MT_ + mt][kc4 * 4]);
#pragma unroll
                    for (int g = 0; g < 4; ++g)
                        acc[mt][g] += w[g].x * h.x + w[g].y * h.y +
                                      w[g].z * h.z + w[g].w * h.w;
                }
            }
            // recurrent contribution: whh1 x h1[cur]
#pragma unroll 2
            for (int kc4 = 0; kc4 < 64; ++kc4) {
                float4 w[4];
#pragma unroll
                for (int g = 0; g < 4; ++g)
                    w[g] = g_w1h[kc4 * G4_ + g * H_ + j];
#pragma unroll
                for (int mt = 0; mt < MT_; ++mt) {
                    float4 h = *reinterpret_cast<const float4*>(
                        &S->h1[cur][gb * MT_ + mt][kc4 * 4]);
#pragma unroll
                    for (int g = 0; g < 4; ++g)
                        acc[mt][g] += w[g].x * h.x + w[g].y * h.y +
                                      w[g].z * h.z + w[g].w * h.w;
                }
            }
#pragma unroll
            for (int mt = 0; mt < MT_; ++mt) {
                int m = gb * MT_ + mt;
                float ig = sigf(acc[mt][0]);
                float fg = sigf(acc[mt][1]);
                float gv = tanhf_(acc[mt][2]);
                float og = sigf(acc[mt][3]);
                float c  = fg * S->c1[m][j] + ig * gv;
                S->c1[m][j]       = c;
                S->h1[nxt][m][j]  = og * tanhf_(c);
            }
        }

        if (t + 1 < T_) {
            for (int idx = tid; idx < M_ * I_; idx += NTHR_) {
                int m = idx / I_, k = idx % I_;
                S->xs[m][k] = x[((size_t)(row0 + m) * T_ + (t + 1)) * I_ + k];
            }
        }
        __syncthreads();
        cur = nxt;
    }

    // ================= FC head =================
    for (int idx = tid; idx < M_ * 2 * P_; idx += NTHR_) {
        int m = idx / (2 * P_), q = idx % (2 * P_);
        const float* wq = fcw + (size_t)q * H_;
        const float* hq = &S->h1[cur][m][0];
        float s = fcb[q];
#pragma unroll 4
        for (int k = 0; k < H_; k += 4) {
            float4 w4 = *reinterpret_cast<const float4*>(wq + k);
            float4 h4 = *reinterpret_cast<const float4*>(hq + k);
            s += w4.x * h4.x + w4.y * h4.y + w4.z * h4.z + w4.w * h4.w;
        }
        S->raw[m][q] = s;
    }
    __syncthreads();

    // ================= kinematic rollout =================
    if (tid < M_) {
        const int m   = tid;
        const int row = row0 + m;
        const float* xl = x + ((size_t)row * T_ + (T_ - 1)) * I_;
        float psi = atan2f(xl[7], xl[8]);
        float X   = xl[0] * IMGW_;
        float Y   = xl[1] * IMGH_;
        float decay = 1.f;
        float* o = out + (size_t)row * P_ * 2;
#pragma unroll 1
        for (int p = 0; p < P_; ++p) {
            float sraw = S->raw[m][2 * p];
            float yaw  = S->raw[m][2 * p + 1];
            float speed = fmaxf(sraw, 0.f) + log1pf(expf(-fabsf(sraw)));
            float w = yaw * decay;
            decay *= 0.97f;
            float v = speed * DIAG_;
            float psi_prev  = psi;
            float psi_after = psi + w * DT_;
            psi = psi_after;
            float is_s  = (fabsf(w) < 0.01f) ? 1.f : 0.f;
            float wsafe = w + is_s * 0.0001f;
            float radius = v / wsafe;
            float sp = sinf(psi_prev),  cp = cosf(psi_prev);
            float sa = sinf(psi_after), ca = cosf(psi_after);
            float dxs = v * cp * DT_;
            float dys = v * sp * DT_;
            float dxt = radius * (sa - sp);
            float dyt = -radius * (ca - cp);
            float dx = is_s * dxs + (1.f - is_s) * dxt;
            float dy = is_s * dys + (1.f - is_s) * dyt;
            X += dx;
            Y += dy;
            o[2 * p]     = X / IMGW_;
            o[2 * p + 1] = Y / IMGH_;
        }
    }
}

extern "C" void kernel_launch(void* const* d_in, const int* in_sizes, int n_in,
                              void* d_out, int out_size)
{
    (void)in_sizes; (void)n_in; (void)out_size;
    const float* x    = (const float*)d_in[0];
    const float* wih0 = (const float*)d_in[1];
    const float* whh0 = (const float*)d_in[2];
    const float* bih0 = (const float*)d_in[3];
    const float* bhh0 = (const float*)d_in[4];
    const float* wih1 = (const float*)d_in[5];
    const float* whh1 = (const float*)d_in[6];
    const float* bih1 = (const float*)d_in[7];
    const float* bhh1 = (const float*)d_in[8];
    const float* fcw  = (const float*)d_in[9];
    const float* fcb  = (const float*)d_in[10];
    float* out = (float*)d_out;

    prep_kernel<<<(64 * G4_ + 255) / 256, 256>>>(whh0, wih1, whh1, wih0);

    cudaFuncSetAttribute(lstm_kin_kernel,
                         cudaFuncAttributeMaxDynamicSharedMemorySize,
                         (int)SMEM_BYTES);

    lstm_kin_kernel<<<NCTA_, NTHR_, SMEM_BYTES>>>(
        x, bih0, bhh0, bih1, bhh1, fcw, fcb, out);
}

// round 4
// speedup vs baseline: 3.4773x; 1.2201x over previous
#include <cuda_runtime.h>
#include <math.h>

// Problem constants
#define B_    4096
#define T_    50
#define I_    17
#define H_    256
#define P_    20
#define M_    32            // batch rows per CTA
#define NGRP_ 2             // thread groups (each owns M_/NGRP_ rows)
#define MG_   (M_ / NGRP_)  // 16 rows per group
#define MT_   8             // row tile per accumulator group
#define NG_   (MG_ / MT_)   // 2 tiles per group
#define NCTA_ (B_ / M_)     // 128 CTAs
#define NTHR_ 512           // 2 groups x 256 columns
#define G4_   (4 * H_)      // 1024 gate rows

#define DT_   0.1f
#define IMGW_ 1920.0f
#define IMGH_ 1080.0f
#define DIAG_ 2202.9071700822507f

// ---------------- transposed-weight scratch (K-major, float4-packed) ----------
// wT[k4][r] = float4( w[r][4*k4 + 0..3] ),  r = g*H + j
__device__ float4 g_w0h[64 * G4_];   // whh0 transposed   (1 MB)
__device__ float4 g_w1i[64 * G4_];   // wih1 transposed   (1 MB)
__device__ float4 g_w1h[64 * G4_];   // whh1 transposed   (1 MB)
__device__ float  g_w0i[I_ * G4_];   // wih0 transposed: g_w0i[k*1024 + r]

__global__ void prep_kernel(const float* __restrict__ whh0,
                            const float* __restrict__ wih1,
                            const float* __restrict__ whh1,
                            const float* __restrict__ wih0)
{
    int idx = blockIdx.x * blockDim.x + threadIdx.x;   // 0 .. 65535
    if (idx < 64 * G4_) {
        int k4 = idx >> 10;
        int r  = idx & (G4_ - 1);
        const float4* s0 = reinterpret_cast<const float4*>(whh0);
        const float4* s1 = reinterpret_cast<const float4*>(wih1);
        const float4* s2 = reinterpret_cast<const float4*>(whh1);
        g_w0h[idx] = s0[r * 64 + k4];
        g_w1i[idx] = s1[r * 64 + k4];
        g_w1h[idx] = s2[r * 64 + k4];
    }
    if (idx < I_ * G4_) {
        int k = idx >> 10;
        int r = idx & (G4_ - 1);
        g_w0i[idx] = wih0[r * I_ + k];
    }
}

// ------------------------------ main kernel ----------------------------------
struct Smem {
    float h0[2][M_][H_];   // layer-0 hidden, double buffered
    float h1[2][M_][H_];   // layer-1 hidden, double buffered
    float c0[M_][H_];      // layer-0 cell
    float c1[M_][H_];      // layer-1 cell
    float xs[M_][I_];      // current timestep input slice
    float raw[M_][2 * P_]; // FC outputs
};
#define SMEM_BYTES (sizeof(Smem))

__device__ __forceinline__ float sigf(float x) {
    return __fdividef(1.f, 1.f + __expf(-x));
}
__device__ __forceinline__ float tanhf_(float x) {
    return __fdividef(2.f, 1.f + __expf(-2.f * x)) - 1.f;
}

// One gb-tile of a GEMV: acc[mt][g] += sum_k wT[k][g*H+j] * hsrc[row][k]
__device__ __forceinline__ void gemv_tile(
    float acc[MT_][4], const float4* __restrict__ wT_j, // = wT + j
    const float (*hsrc)[H_], int row0)
{
#pragma unroll 2
    for (int kc4 = 0; kc4 < 64; ++kc4) {
        float4 w[4];
#pragma unroll
        for (int g = 0; g < 4; ++g)
            w[g] = wT_j[kc4 * G4_ + g * H_];
#pragma unroll
        for (int mt = 0; mt < MT_; ++mt) {
            float4 h = *reinterpret_cast<const float4*>(&hsrc[row0 + mt][kc4 * 4]);
#pragma unroll
            for (int g = 0; g < 4; ++g)
                acc[mt][g] += w[g].x * h.x + w[g].y * h.y +
                              w[g].z * h.z + w[g].w * h.w;
        }
    }
}

__global__ void __launch_bounds__(NTHR_, 1)
lstm_kin_kernel(const float* __restrict__ x,
                const float* __restrict__ bih0, const float* __restrict__ bhh0,
                const float* __restrict__ bih1, const float* __restrict__ bhh1,
                const float* __restrict__ fcw,  const float* __restrict__ fcb,
                float* __restrict__ out)
{
    extern __shared__ float smem_raw[];
    Smem* S = reinterpret_cast<Smem*>(smem_raw);

    const int tid  = threadIdx.x;
    const int j    = tid & (H_ - 1);      // hidden column
    const int grp  = tid >> 8;            // row group (0/1)
    const int row0 = blockIdx.x * M_;
    const int mg0  = grp * MG_;           // first row owned by this group

    float bias0[4], bias1[4];
#pragma unroll
    for (int g = 0; g < 4; ++g) {
        bias0[g] = bih0[g * H_ + j] + bhh0[g * H_ + j];
        bias1[g] = bih1[g * H_ + j] + bhh1[g * H_ + j];
    }

    const float4* __restrict__ w0h_j = g_w0h + j;
    const float4* __restrict__ w1i_j = g_w1i + j;
    const float4* __restrict__ w1h_j = g_w1h + j;

    // Zero this group's state
#pragma unroll
    for (int m = mg0; m < mg0 + MG_; ++m) {
        S->h0[0][m][j] = 0.f;
        S->h1[0][m][j] = 0.f;
        S->c0[m][j]    = 0.f;
        S->c1[m][j]    = 0.f;
    }
    for (int idx = tid; idx < M_ * I_; idx += NTHR_) {
        int m = idx / I_, k = idx % I_;
        S->xs[m][k] = x[((size_t)(row0 + m) * T_ + 0) * I_ + k];
    }
    __syncthreads();

    int cur = 0;
    for (int t = 0; t < T_; ++t) {
        const int nxt = cur ^ 1;

        // ================= layer 0 =================
#pragma unroll 1
        for (int gb = 0; gb < NG_; ++gb) {
            const int r0 = mg0 + gb * MT_;
            float acc[MT_][4];
#pragma unroll
            for (int mt = 0; mt < MT_; ++mt)
#pragma unroll
                for (int g = 0; g < 4; ++g) acc[mt][g] = bias0[g];

            // input contribution (K = 17)
#pragma unroll
            for (int k = 0; k < I_; ++k) {
                float wv0 = g_w0i[k * G4_ + 0 * H_ + j];
                float wv1 = g_w0i[k * G4_ + 1 * H_ + j];
                float wv2 = g_w0i[k * G4_ + 2 * H_ + j];
                float wv3 = g_w0i[k * G4_ + 3 * H_ + j];
#pragma unroll
                for (int mt = 0; mt < MT_; ++mt) {
                    float xv = S->xs[r0 + mt][k];
                    acc[mt][0] += wv0 * xv;
                    acc[mt][1] += wv1 * xv;
                    acc[mt][2] += wv2 * xv;
                    acc[mt][3] += wv3 * xv;
                }
            }
            // recurrent contribution (K = 256)
            gemv_tile(acc, w0h_j, S->h0[cur], r0);

#pragma unroll
            for (int mt = 0; mt < MT_; ++mt) {
                int m = r0 + mt;
                float ig = sigf(acc[mt][0]);
                float fg = sigf(acc[mt][1]);
                float gv = tanhf_(acc[mt][2]);
                float og = sigf(acc[mt][3]);
                float c  = fg * S->c0[m][j] + ig * gv;
                S->c0[m][j]       = c;
                S->h0[nxt][m][j]  = og * tanhf_(c);
            }
        }
        __syncthreads();

        // ================= layer 1 =================
#pragma unroll 1
        for (int gb = 0; gb < NG_; ++gb) {
            const int r0 = mg0 + gb * MT_;
            float acc[MT_][4];
#pragma unroll
            for (int mt = 0; mt < MT_; ++mt)
#pragma unroll
                for (int g = 0; g < 4; ++g) acc[mt][g] = bias1[g];

            gemv_tile(acc, w1i_j, S->h0[nxt], r0);   // wih1 x h0[nxt]
            gemv_tile(acc, w1h_j, S->h1[cur], r0);   // whh1 x h1[cur]

#pragma unroll
            for (int mt = 0; mt < MT_; ++mt) {
                int m = r0 + mt;
                float ig = sigf(acc[mt][0]);
                float fg = sigf(acc[mt][1]);
                float gv = tanhf_(acc[mt][2]);
                float og = sigf(acc[mt][3]);
                float c  = fg * S->c1[m][j] + ig * gv;
                S->c1[m][j]       = c;
                S->h1[nxt][m][j]  = og * tanhf_(c);
            }
        }

        if (t + 1 < T_) {
            for (int idx = tid; idx < M_ * I_; idx += NTHR_) {
                int m = idx / I_, k = idx % I_;
                S->xs[m][k] = x[((size_t)(row0 + m) * T_ + (t + 1)) * I_ + k];
            }
        }
        __syncthreads();
        cur = nxt;
    }

    // ================= FC head =================
    for (int idx = tid; idx < M_ * 2 * P_; idx += NTHR_) {
        int m = idx / (2 * P_), q = idx % (2 * P_);
        const float* wq = fcw + (size_t)q * H_;
        const float* hq = &S->h1[cur][m][0];
        float s = fcb[q];
#pragma unroll 4
        for (int k = 0; k < H_; k += 4) {
            float4 w4 = *reinterpret_cast<const float4*>(wq + k);
            float4 h4 = *reinterpret_cast<const float4*>(hq + k);
            s += w4.x * h4.x + w4.y * h4.y + w4.z * h4.z + w4.w * h4.w;
        }
        S->raw[m][q] = s;
    }
    __syncthreads();

    // ================= kinematic rollout =================
    if (tid < M_) {
        const int m   = tid;
        const int row = row0 + m;
        const float* xl = x + ((size_t)row * T_ + (T_ - 1)) * I_;
        float psi = atan2f(xl[7], xl[8]);
        float X   = xl[0] * IMGW_;
        float Y   = xl[1] * IMGH_;
        float decay = 1.f;
        float* o = out + (size_t)row * P_ * 2;
#pragma unroll 1
        for (int p = 0; p < P_; ++p) {
            float sraw = S->raw[m][2 * p];
            float yaw  = S->raw[m][2 * p + 1];
            float speed = fmaxf(sraw, 0.f) + log1pf(expf(-fabsf(sraw)));
            float w = yaw * decay;
            decay *= 0.97f;
            float v = speed * DIAG_;
            float psi_prev  = psi;
            float psi_after = psi + w * DT_;
            psi = psi_after;
            float is_s  = (fabsf(w) < 0.01f) ? 1.f : 0.f;
            float wsafe = w + is_s * 0.0001f;
            float radius = v / wsafe;
            float sp = sinf(psi_prev),  cp = cosf(psi_prev);
            float sa = sinf(psi_after), ca = cosf(psi_after);
            float dxs = v * cp * DT_;
            float dys = v * sp * DT_;
            float dxt = radius * (sa - sp);
            float dyt = -radius * (ca - cp);
            float dx = is_s * dxs + (1.f - is_s) * dxt;
            float dy = is_s * dys + (1.f - is_s) * dyt;
            X += dx;
            Y += dy;
            o[2 * p]     = X / IMGW_;
            o[2 * p + 1] = Y / IMGH_;
        }
    }
}

extern "C" void kernel_launch(void* const* d_in, const int* in_sizes, int n_in,
                              void* d_out, int out_size)
{
    (void)in_sizes; (void)n_in; (void)out_size;
    const float* x    = (const float*)d_in[0];
    const float* wih0 = (const float*)d_in[1];
    const float* whh0 = (const float*)d_in[2];
    const float* bih0 = (const float*)d_in[3];
    const float* bhh0 = (const float*)d_in[4];
    const float* wih1 = (const float*)d_in[5];
    const float* whh1 = (const float*)d_in[6];
    const float* bih1 = (const float*)d_in[7];
    const float* bhh1 = (const float*)d_in[8];
    const float* fcw  = (const float*)d_in[9];
    const float* fcb  = (const float*)d_in[10];
    float* out = (float*)d_out;

    prep_kernel<<<(64 * G4_ + 255) / 256, 256>>>(whh0, wih1, whh1, wih0);

    cudaFuncSetAttribute(lstm_kin_kernel,
                         cudaFuncAttributeMaxDynamicSharedMemorySize,
                         (int)SMEM_BYTES);

    lstm_kin_kernel<<<NCTA_, NTHR_, SMEM_BYTES>>>(
        x, bih0, bhh0, bih1, bhh1, fcw, fcb, out);
}